// round 1
// baseline (speedup 1.0000x reference)
#include <cuda_runtime.h>
#include <math.h>

// Problem constants
#define BATCH 4
#define TSZ   1024
#define DIM   1024
#define NHEAD 16
#define HDIM  64
#define C3    (3 * DIM)

// Scratch (allocation-free: __device__ globals)
__device__ float g_qkv[BATCH * TSZ * C3];   // [B,T,3C]
__device__ float g_att[BATCH * TSZ * DIM];  // [B,T,C]

// ---------------------------------------------------------------------------
// SGEMM (NT): C[m,n] = sum_k A[m,k] * B[n,k] (+ bias[n])
// A: M x K row-major, B: N x K row-major. M,N multiples of 128, K mult of 8.
// Block 128x128, BK=8, 256 threads, 8x8 per-thread tile.
// ---------------------------------------------------------------------------
template <bool BIAS>
__global__ __launch_bounds__(256)
void sgemm_nt(const float* __restrict__ A, const float* __restrict__ B,
              const float* __restrict__ bias, float* __restrict__ C,
              int M, int N, int K) {
    __shared__ float As[8 * 132];  // As[kk*132 + r], padded
    __shared__ float Bs[8 * 132];

    const int tid = threadIdx.x;
    const int tx = tid & 15;        // 0..15 -> col group
    const int ty = tid >> 4;        // 0..15 -> row group
    const int bm = blockIdx.y * 128;
    const int bn = blockIdx.x * 128;

    const int lr = tid >> 1;        // 0..127 load row
    const int lk = (tid & 1) << 2;  // 0 or 4

    float acc[8][8];
#pragma unroll
    for (int i = 0; i < 8; i++)
#pragma unroll
        for (int j = 0; j < 8; j++) acc[i][j] = 0.f;

    const float* Aptr = A + (size_t)(bm + lr) * K + lk;
    const float* Bptr = B + (size_t)(bn + lr) * K + lk;

    for (int k0 = 0; k0 < K; k0 += 8) {
        float4 av = *(const float4*)(Aptr + k0);
        float4 bv = *(const float4*)(Bptr + k0);
        __syncthreads();
        As[(lk + 0) * 132 + lr] = av.x;
        As[(lk + 1) * 132 + lr] = av.y;
        As[(lk + 2) * 132 + lr] = av.z;
        As[(lk + 3) * 132 + lr] = av.w;
        Bs[(lk + 0) * 132 + lr] = bv.x;
        Bs[(lk + 1) * 132 + lr] = bv.y;
        Bs[(lk + 2) * 132 + lr] = bv.z;
        Bs[(lk + 3) * 132 + lr] = bv.w;
        __syncthreads();
#pragma unroll
        for (int kk = 0; kk < 8; kk++) {
            float4 a0 = *(const float4*)&As[kk * 132 + ty * 8];
            float4 a1 = *(const float4*)&As[kk * 132 + ty * 8 + 4];
            float4 b0 = *(const float4*)&Bs[kk * 132 + tx * 8];
            float4 b1 = *(const float4*)&Bs[kk * 132 + tx * 8 + 4];
            float ar[8] = {a0.x, a0.y, a0.z, a0.w, a1.x, a1.y, a1.z, a1.w};
            float br[8] = {b0.x, b0.y, b0.z, b0.w, b1.x, b1.y, b1.z, b1.w};
#pragma unroll
            for (int i = 0; i < 8; i++)
#pragma unroll
                for (int j = 0; j < 8; j++) acc[i][j] = fmaf(ar[i], br[j], acc[i][j]);
        }
    }

    // Epilogue
#pragma unroll
    for (int i = 0; i < 8; i++) {
        int row = bm + ty * 8 + i;
        float* crow = C + (size_t)row * N + bn + tx * 8;
#pragma unroll
        for (int j4 = 0; j4 < 2; j4++) {
            float4 v;
            v.x = acc[i][j4 * 4 + 0];
            v.y = acc[i][j4 * 4 + 1];
            v.z = acc[i][j4 * 4 + 2];
            v.w = acc[i][j4 * 4 + 3];
            if (BIAS) {
                const float* bp = bias + bn + tx * 8 + j4 * 4;
                v.x += bp[0]; v.y += bp[1]; v.z += bp[2]; v.w += bp[3];
            }
            *(float4*)(crow + j4 * 4) = v;
        }
    }
}

// ---------------------------------------------------------------------------
// Flash attention: per block = 64 q-rows of one (b,h); stream 16 kv-tiles of 64.
// Thread layout 16x16; thread (tx,ty) owns S/P rows ty*4..+3, cols tx*4..+3,
// and O rows ty*4..+3, d-cols tx*4..+3.
// ---------------------------------------------------------------------------
#define SMEM_STRIDE 68
#define FLASH_SMEM (4 * 64 * SMEM_STRIDE * 4)

__global__ __launch_bounds__(256)
void flash_kernel(const float* __restrict__ qkv, float* __restrict__ att) {
    extern __shared__ float sm[];
    float* sQ = sm;                          // sQ[d][r] transposed
    float* sK = sm + 64 * SMEM_STRIDE;       // sK[d][c] transposed
    float* sV = sm + 2 * 64 * SMEM_STRIDE;   // sV[j][d]
    float* sP = sm + 3 * 64 * SMEM_STRIDE;   // sP[j][r] transposed

    const int tid = threadIdx.x;
    const int tx = tid & 15;
    const int ty = tid >> 4;
    const int bh = blockIdx.y;
    const int b = bh >> 4;
    const int h = bh & 15;
    const int t0 = blockIdx.x * 64;
    const size_t base = (size_t)b * TSZ * C3;
    const int hoff = h * HDIM;
    const float scale = 0.125f;  // 1/sqrt(64)

    // Load Q tile transposed
    for (int i = tid; i < 64 * 64; i += 256) {
        int r = i >> 6, d = i & 63;
        sQ[d * SMEM_STRIDE + r] = qkv[base + (size_t)(t0 + r) * C3 + hoff + d];
    }

    float mrow[4], lrow[4], o[4][4];
#pragma unroll
    for (int i = 0; i < 4; i++) {
        mrow[i] = -INFINITY;
        lrow[i] = 0.f;
#pragma unroll
        for (int j = 0; j < 4; j++) o[i][j] = 0.f;
    }

    for (int kt = 0; kt < 16; kt++) {
        const int tk0 = kt * 64;
        __syncthreads();  // prior readers of sK/sV/sP done; iter0: nothing pending
        for (int i = tid; i < 64 * 64; i += 256) {
            int c = i >> 6, d = i & 63;
            const float* row = qkv + base + (size_t)(tk0 + c) * C3 + hoff + d;
            sK[d * SMEM_STRIDE + c] = row[DIM];       // K
            sV[c * SMEM_STRIDE + d] = row[2 * DIM];   // V
        }
        __syncthreads();

        // S = scale * Q K^T  (64x64 tile; 4x4 per thread)
        float acc[4][4];
#pragma unroll
        for (int i = 0; i < 4; i++)
#pragma unroll
            for (int j = 0; j < 4; j++) acc[i][j] = 0.f;
#pragma unroll 8
        for (int d = 0; d < 64; d++) {
            float4 a = *(const float4*)&sQ[d * SMEM_STRIDE + ty * 4];
            float4 bb = *(const float4*)&sK[d * SMEM_STRIDE + tx * 4];
            float ar[4] = {a.x, a.y, a.z, a.w};
            float br[4] = {bb.x, bb.y, bb.z, bb.w};
#pragma unroll
            for (int i = 0; i < 4; i++)
#pragma unroll
                for (int j = 0; j < 4; j++) acc[i][j] = fmaf(ar[i], br[j], acc[i][j]);
        }

        // Online softmax per row (reduce across tx = 16 lanes of the warp)
#pragma unroll
        for (int i = 0; i < 4; i++) {
            float rmax = -INFINITY;
#pragma unroll
            for (int j = 0; j < 4; j++) {
                acc[i][j] *= scale;
                rmax = fmaxf(rmax, acc[i][j]);
            }
#pragma unroll
            for (int off = 8; off >= 1; off >>= 1)
                rmax = fmaxf(rmax, __shfl_xor_sync(0xffffffffu, rmax, off, 16));
            float mn = fmaxf(mrow[i], rmax);
            float alpha = __expf(mrow[i] - mn);
            float p[4], rs = 0.f;
#pragma unroll
            for (int j = 0; j < 4; j++) {
                p[j] = __expf(acc[i][j] - mn);
                rs += p[j];
            }
#pragma unroll
            for (int off = 8; off >= 1; off >>= 1)
                rs += __shfl_xor_sync(0xffffffffu, rs, off, 16);
            lrow[i] = lrow[i] * alpha + rs;
            mrow[i] = mn;
#pragma unroll
            for (int j = 0; j < 4; j++) o[i][j] *= alpha;
#pragma unroll
            for (int j = 0; j < 4; j++)
                sP[(tx * 4 + j) * SMEM_STRIDE + (ty * 4 + i)] = p[j];
        }
        __syncthreads();

        // O += P V  (inner over 64 kv)
#pragma unroll 8
        for (int j = 0; j < 64; j++) {
            float4 a = *(const float4*)&sP[j * SMEM_STRIDE + ty * 4];
            float4 bb = *(const float4*)&sV[j * SMEM_STRIDE + tx * 4];
            float ar[4] = {a.x, a.y, a.z, a.w};
            float br[4] = {bb.x, bb.y, bb.z, bb.w};
#pragma unroll
            for (int i = 0; i < 4; i++)
#pragma unroll
                for (int jj = 0; jj < 4; jj++) o[i][jj] = fmaf(ar[i], br[jj], o[i][jj]);
        }
    }

    // Epilogue: normalize, write to g_att [B,T,C]
#pragma unroll
    for (int i = 0; i < 4; i++) {
        float inv = 1.f / lrow[i];
        int r = t0 + ty * 4 + i;
        float4 v;
        v.x = o[i][0] * inv; v.y = o[i][1] * inv;
        v.z = o[i][2] * inv; v.w = o[i][3] * inv;
        *(float4*)(att + (size_t)b * TSZ * DIM + (size_t)r * DIM + hoff + tx * 4) = v;
    }
}

// ---------------------------------------------------------------------------
extern "C" void kernel_launch(void* const* d_in, const int* in_sizes, int n_in,
                              void* d_out, int out_size) {
    const float* x     = (const float*)d_in[0];  // [4,1024,1024]
    const float* Wqkv  = (const float*)d_in[1];  // [3072,1024]
    const float* Wproj = (const float*)d_in[2];  // [1024,1024]
    const float* bproj = (const float*)d_in[3];  // [1024]
    float* out = (float*)d_out;                  // [4,1024,1024]

    float *qkv, *att;
    cudaGetSymbolAddress((void**)&qkv, g_qkv);
    cudaGetSymbolAddress((void**)&att, g_att);

    // 1) QKV projection: [4096,1024] x [3072,1024]^T -> [4096,3072]
    sgemm_nt<false><<<dim3(C3 / 128, (BATCH * TSZ) / 128), 256>>>(
        x, Wqkv, nullptr, qkv, BATCH * TSZ, C3, DIM);

    // 2) Attention
    cudaFuncSetAttribute(flash_kernel, cudaFuncAttributeMaxDynamicSharedMemorySize,
                         FLASH_SMEM);
    flash_kernel<<<dim3(TSZ / 64, BATCH * NHEAD), 256, FLASH_SMEM>>>(qkv, att);

    // 3) Output projection + bias: [4096,1024] x [1024,1024]^T -> [4096,1024]
    sgemm_nt<true><<<dim3(DIM / 128, (BATCH * TSZ) / 128), 256>>>(
        att, Wproj, bproj, out, BATCH * TSZ, DIM, DIM);
}

// round 2
// speedup vs baseline: 1.5516x; 1.5516x over previous
#include <cuda_runtime.h>
#include <math.h>
#include <stdint.h>

// Problem constants
#define BATCH 4
#define TSZ   1024
#define DIM   1024
#define NHEAD 16
#define HDIM  64
#define C3    (3 * DIM)

// Scratch (allocation-free: __device__ globals)
__device__ float g_qkv[BATCH * TSZ * C3];   // [B,T,3C]
__device__ float g_att[BATCH * TSZ * DIM];  // [B,T,C]

// ---------------------------------------------------------------------------
// tf32 helpers
// ---------------------------------------------------------------------------
__device__ __forceinline__ uint32_t f2tf(float f) {
    uint32_t u;
    asm("cvt.rna.tf32.f32 %0, %1;" : "=r"(u) : "f"(f));
    return u;
}

__device__ __forceinline__ void mma_tf32(float c[4], const uint32_t a[4],
                                         const uint32_t b[2]) {
    asm volatile(
        "mma.sync.aligned.m16n8k8.row.col.f32.tf32.tf32.f32 "
        "{%0,%1,%2,%3}, {%4,%5,%6,%7}, {%8,%9}, {%0,%1,%2,%3};"
        : "+f"(c[0]), "+f"(c[1]), "+f"(c[2]), "+f"(c[3])
        : "r"(a[0]), "r"(a[1]), "r"(a[2]), "r"(a[3]), "r"(b[0]), "r"(b[1]));
}

// ---------------------------------------------------------------------------
// TF32 GEMM (NT): C[m,n] = sum_k A[m,k]*B[n,k] (+bias[n])
// Block 128x128, BK=16, 256 threads = 8 warps (2x4), warp tile 64x32.
// Double-buffered smem, stride 20 (conflict-free fragment loads).
// ---------------------------------------------------------------------------
#define BK 16
#define ASTR 20

template <bool BIAS>
__global__ __launch_bounds__(256)
void tf32_gemm_nt(const float* __restrict__ A, const float* __restrict__ B,
                  const float* __restrict__ bias, float* __restrict__ C,
                  int M, int N, int K) {
    __shared__ uint32_t sA[2][128 * ASTR];
    __shared__ uint32_t sB[2][128 * ASTR];

    const int tid  = threadIdx.x;
    const int lane = tid & 31;
    const int warp = tid >> 5;
    const int g = lane >> 2;      // 0..7
    const int t = lane & 3;       // 0..3
    const int wm = (warp >> 2) * 64;  // 0 or 64
    const int wn = (warp & 3) * 32;   // 0,32,64,96
    const int bm = blockIdx.y * 128;
    const int bn = blockIdx.x * 128;

    // Global->smem mapping: thread owns row lrow, 8 consecutive k at lkq
    const int lrow = tid >> 1;        // 0..127
    const int lkq  = (tid & 1) * 8;   // 0 or 8

    const float* Ap = A + (size_t)(bm + lrow) * K + lkq;
    const float* Bp = B + (size_t)(bn + lrow) * K + lkq;

    float acc[16][4];
#pragma unroll
    for (int i = 0; i < 16; i++)
#pragma unroll
        for (int j = 0; j < 4; j++) acc[i][j] = 0.f;

    float4 ra0, ra1, rb0, rb1;
    ra0 = *(const float4*)(Ap);
    ra1 = *(const float4*)(Ap + 4);
    rb0 = *(const float4*)(Bp);
    rb1 = *(const float4*)(Bp + 4);

    const int sbase = lrow * ASTR + lkq;
    {
        uint4 u;
        u.x = f2tf(ra0.x); u.y = f2tf(ra0.y); u.z = f2tf(ra0.z); u.w = f2tf(ra0.w);
        *(uint4*)&sA[0][sbase] = u;
        u.x = f2tf(ra1.x); u.y = f2tf(ra1.y); u.z = f2tf(ra1.z); u.w = f2tf(ra1.w);
        *(uint4*)&sA[0][sbase + 4] = u;
        u.x = f2tf(rb0.x); u.y = f2tf(rb0.y); u.z = f2tf(rb0.z); u.w = f2tf(rb0.w);
        *(uint4*)&sB[0][sbase] = u;
        u.x = f2tf(rb1.x); u.y = f2tf(rb1.y); u.z = f2tf(rb1.z); u.w = f2tf(rb1.w);
        *(uint4*)&sB[0][sbase + 4] = u;
    }
    __syncthreads();

    const int NT = K / BK;
    int buf = 0;
    for (int kt = 0; kt < NT; kt++) {
        if (kt + 1 < NT) {
            const float* ap = Ap + (kt + 1) * BK;
            const float* bp = Bp + (kt + 1) * BK;
            ra0 = *(const float4*)(ap);
            ra1 = *(const float4*)(ap + 4);
            rb0 = *(const float4*)(bp);
            rb1 = *(const float4*)(bp + 4);
        }

#pragma unroll
        for (int kk = 0; kk < 2; kk++) {
            uint32_t af[4][4], bf[4][2];
            const int ko = kk * 8 + t;
#pragma unroll
            for (int mt = 0; mt < 4; mt++) {
                const int rb = wm + mt * 16 + g;
                af[mt][0] = sA[buf][rb * ASTR + ko];
                af[mt][1] = sA[buf][(rb + 8) * ASTR + ko];
                af[mt][2] = sA[buf][rb * ASTR + ko + 4];
                af[mt][3] = sA[buf][(rb + 8) * ASTR + ko + 4];
            }
#pragma unroll
            for (int nt = 0; nt < 4; nt++) {
                const int nb = wn + nt * 8 + g;
                bf[nt][0] = sB[buf][nb * ASTR + ko];
                bf[nt][1] = sB[buf][nb * ASTR + ko + 4];
            }
#pragma unroll
            for (int mt = 0; mt < 4; mt++)
#pragma unroll
                for (int nt = 0; nt < 4; nt++)
                    mma_tf32(acc[mt * 4 + nt], af[mt], bf[nt]);
        }

        if (kt + 1 < NT) {
            const int nb = buf ^ 1;
            uint4 u;
            u.x = f2tf(ra0.x); u.y = f2tf(ra0.y); u.z = f2tf(ra0.z); u.w = f2tf(ra0.w);
            *(uint4*)&sA[nb][sbase] = u;
            u.x = f2tf(ra1.x); u.y = f2tf(ra1.y); u.z = f2tf(ra1.z); u.w = f2tf(ra1.w);
            *(uint4*)&sA[nb][sbase + 4] = u;
            u.x = f2tf(rb0.x); u.y = f2tf(rb0.y); u.z = f2tf(rb0.z); u.w = f2tf(rb0.w);
            *(uint4*)&sB[nb][sbase] = u;
            u.x = f2tf(rb1.x); u.y = f2tf(rb1.y); u.z = f2tf(rb1.z); u.w = f2tf(rb1.w);
            *(uint4*)&sB[nb][sbase + 4] = u;
            __syncthreads();
            buf = nb;
        }
    }

    // Epilogue: C frag (row g / g+8, cols 2t, 2t+1)
#pragma unroll
    for (int mt = 0; mt < 4; mt++) {
#pragma unroll
        for (int nt = 0; nt < 4; nt++) {
            const float* a4 = acc[mt * 4 + nt];
            const int row = bm + wm + mt * 16 + g;
            const int col = bn + wn + nt * 8 + 2 * t;
            float bx = 0.f, by = 0.f;
            if (BIAS) { bx = bias[col]; by = bias[col + 1]; }
            float2 v0 = {a4[0] + bx, a4[1] + by};
            float2 v1 = {a4[2] + bx, a4[3] + by};
            *(float2*)(C + (size_t)row * N + col) = v0;
            *(float2*)(C + (size_t)(row + 8) * N + col) = v1;
        }
    }
}

// ---------------------------------------------------------------------------
// Flash attention (fp32 FFMA, unchanged from round 1)
// ---------------------------------------------------------------------------
#define SMEM_STRIDE 68
#define FLASH_SMEM (4 * 64 * SMEM_STRIDE * 4)

__global__ __launch_bounds__(256)
void flash_kernel(const float* __restrict__ qkv, float* __restrict__ att) {
    extern __shared__ float sm[];
    float* sQ = sm;                          // sQ[d][r] transposed
    float* sK = sm + 64 * SMEM_STRIDE;       // sK[d][c] transposed
    float* sV = sm + 2 * 64 * SMEM_STRIDE;   // sV[j][d]
    float* sP = sm + 3 * 64 * SMEM_STRIDE;   // sP[j][r] transposed

    const int tid = threadIdx.x;
    const int tx = tid & 15;
    const int ty = tid >> 4;
    const int bh = blockIdx.y;
    const int b = bh >> 4;
    const int h = bh & 15;
    const int t0 = blockIdx.x * 64;
    const size_t base = (size_t)b * TSZ * C3;
    const int hoff = h * HDIM;
    const float scale = 0.125f;  // 1/sqrt(64)

    for (int i = tid; i < 64 * 64; i += 256) {
        int r = i >> 6, d = i & 63;
        sQ[d * SMEM_STRIDE + r] = qkv[base + (size_t)(t0 + r) * C3 + hoff + d];
    }

    float mrow[4], lrow[4], o[4][4];
#pragma unroll
    for (int i = 0; i < 4; i++) {
        mrow[i] = -INFINITY;
        lrow[i] = 0.f;
#pragma unroll
        for (int j = 0; j < 4; j++) o[i][j] = 0.f;
    }

    for (int kt = 0; kt < 16; kt++) {
        const int tk0 = kt * 64;
        __syncthreads();
        for (int i = tid; i < 64 * 64; i += 256) {
            int c = i >> 6, d = i & 63;
            const float* row = qkv + base + (size_t)(tk0 + c) * C3 + hoff + d;
            sK[d * SMEM_STRIDE + c] = row[DIM];       // K
            sV[c * SMEM_STRIDE + d] = row[2 * DIM];   // V
        }
        __syncthreads();

        float acc[4][4];
#pragma unroll
        for (int i = 0; i < 4; i++)
#pragma unroll
            for (int j = 0; j < 4; j++) acc[i][j] = 0.f;
#pragma unroll 8
        for (int d = 0; d < 64; d++) {
            float4 a = *(const float4*)&sQ[d * SMEM_STRIDE + ty * 4];
            float4 bb = *(const float4*)&sK[d * SMEM_STRIDE + tx * 4];
            float ar[4] = {a.x, a.y, a.z, a.w};
            float br[4] = {bb.x, bb.y, bb.z, bb.w};
#pragma unroll
            for (int i = 0; i < 4; i++)
#pragma unroll
                for (int j = 0; j < 4; j++) acc[i][j] = fmaf(ar[i], br[j], acc[i][j]);
        }

#pragma unroll
        for (int i = 0; i < 4; i++) {
            float rmax = -INFINITY;
#pragma unroll
            for (int j = 0; j < 4; j++) {
                acc[i][j] *= scale;
                rmax = fmaxf(rmax, acc[i][j]);
            }
#pragma unroll
            for (int off = 8; off >= 1; off >>= 1)
                rmax = fmaxf(rmax, __shfl_xor_sync(0xffffffffu, rmax, off, 16));
            float mn = fmaxf(mrow[i], rmax);
            float alpha = __expf(mrow[i] - mn);
            float p[4], rs = 0.f;
#pragma unroll
            for (int j = 0; j < 4; j++) {
                p[j] = __expf(acc[i][j] - mn);
                rs += p[j];
            }
#pragma unroll
            for (int off = 8; off >= 1; off >>= 1)
                rs += __shfl_xor_sync(0xffffffffu, rs, off, 16);
            lrow[i] = lrow[i] * alpha + rs;
            mrow[i] = mn;
#pragma unroll
            for (int j = 0; j < 4; j++) o[i][j] *= alpha;
#pragma unroll
            for (int j = 0; j < 4; j++)
                sP[(tx * 4 + j) * SMEM_STRIDE + (ty * 4 + i)] = p[j];
        }
        __syncthreads();

#pragma unroll 8
        for (int j = 0; j < 64; j++) {
            float4 a = *(const float4*)&sP[j * SMEM_STRIDE + ty * 4];
            float4 bb = *(const float4*)&sV[j * SMEM_STRIDE + tx * 4];
            float ar[4] = {a.x, a.y, a.z, a.w};
            float br[4] = {bb.x, bb.y, bb.z, bb.w};
#pragma unroll
            for (int i = 0; i < 4; i++)
#pragma unroll
                for (int jj = 0; jj < 4; jj++) o[i][jj] = fmaf(ar[i], br[jj], o[i][jj]);
        }
    }

#pragma unroll
    for (int i = 0; i < 4; i++) {
        float inv = 1.f / lrow[i];
        int r = t0 + ty * 4 + i;
        float4 v;
        v.x = o[i][0] * inv; v.y = o[i][1] * inv;
        v.z = o[i][2] * inv; v.w = o[i][3] * inv;
        *(float4*)(att + (size_t)b * TSZ * DIM + (size_t)r * DIM + hoff + tx * 4) = v;
    }
}

// ---------------------------------------------------------------------------
extern "C" void kernel_launch(void* const* d_in, const int* in_sizes, int n_in,
                              void* d_out, int out_size) {
    const float* x     = (const float*)d_in[0];  // [4,1024,1024]
    const float* Wqkv  = (const float*)d_in[1];  // [3072,1024]
    const float* Wproj = (const float*)d_in[2];  // [1024,1024]
    const float* bproj = (const float*)d_in[3];  // [1024]
    float* out = (float*)d_out;                  // [4,1024,1024]

    float *qkv, *att;
    cudaGetSymbolAddress((void**)&qkv, g_qkv);
    cudaGetSymbolAddress((void**)&att, g_att);

    // 1) QKV projection: [4096,1024] x [3072,1024]^T -> [4096,3072]
    tf32_gemm_nt<false><<<dim3(C3 / 128, (BATCH * TSZ) / 128), 256>>>(
        x, Wqkv, nullptr, qkv, BATCH * TSZ, C3, DIM);

    // 2) Attention
    cudaFuncSetAttribute(flash_kernel, cudaFuncAttributeMaxDynamicSharedMemorySize,
                         FLASH_SMEM);
    flash_kernel<<<dim3(TSZ / 64, BATCH * NHEAD), 256, FLASH_SMEM>>>(qkv, att);

    // 3) Output projection + bias: [4096,1024] x [1024,1024]^T -> [4096,1024]
    tf32_gemm_nt<true><<<dim3(DIM / 128, (BATCH * TSZ) / 128), 256>>>(
        att, Wproj, bproj, out, BATCH * TSZ, DIM, DIM);
}

// round 3
// speedup vs baseline: 2.2329x; 1.4391x over previous
#include <cuda_runtime.h>
#include <math.h>
#include <stdint.h>

// Problem constants
#define BATCH 4
#define TSZ   1024
#define DIM   1024
#define NHEAD 16
#define HDIM  64
#define C3    (3 * DIM)

// Scratch (allocation-free: __device__ globals)
__device__ float g_qkv[BATCH * TSZ * C3];   // [B,T,3C]
__device__ float g_att[BATCH * TSZ * DIM];  // [B,T,C]

// ---------------------------------------------------------------------------
// tf32 helpers
// ---------------------------------------------------------------------------
__device__ __forceinline__ uint32_t f2tf(float f) {
    uint32_t u;
    asm("cvt.rna.tf32.f32 %0, %1;" : "=r"(u) : "f"(f));
    return u;
}

__device__ __forceinline__ void mma_tf32(float c[4], const uint32_t a[4],
                                         const uint32_t b[2]) {
    asm volatile(
        "mma.sync.aligned.m16n8k8.row.col.f32.tf32.tf32.f32 "
        "{%0,%1,%2,%3}, {%4,%5,%6,%7}, {%8,%9}, {%0,%1,%2,%3};"
        : "+f"(c[0]), "+f"(c[1]), "+f"(c[2]), "+f"(c[3])
        : "r"(a[0]), "r"(a[1]), "r"(a[2]), "r"(a[3]), "r"(b[0]), "r"(b[1]));
}

// ---------------------------------------------------------------------------
// TF32 GEMM (NT): C[m,n] = sum_k A[m,k]*B[n,k] (+bias[n])   (round-2, proven)
// ---------------------------------------------------------------------------
#define BK 16
#define ASTR 20

template <bool BIAS>
__global__ __launch_bounds__(256)
void tf32_gemm_nt(const float* __restrict__ A, const float* __restrict__ B,
                  const float* __restrict__ bias, float* __restrict__ C,
                  int M, int N, int K) {
    __shared__ uint32_t sA[2][128 * ASTR];
    __shared__ uint32_t sB[2][128 * ASTR];

    const int tid  = threadIdx.x;
    const int lane = tid & 31;
    const int warp = tid >> 5;
    const int g = lane >> 2;
    const int t = lane & 3;
    const int wm = (warp >> 2) * 64;
    const int wn = (warp & 3) * 32;
    const int bm = blockIdx.y * 128;
    const int bn = blockIdx.x * 128;

    const int lrow = tid >> 1;
    const int lkq  = (tid & 1) * 8;

    const float* Ap = A + (size_t)(bm + lrow) * K + lkq;
    const float* Bp = B + (size_t)(bn + lrow) * K + lkq;

    float acc[16][4];
#pragma unroll
    for (int i = 0; i < 16; i++)
#pragma unroll
        for (int j = 0; j < 4; j++) acc[i][j] = 0.f;

    float4 ra0, ra1, rb0, rb1;
    ra0 = *(const float4*)(Ap);
    ra1 = *(const float4*)(Ap + 4);
    rb0 = *(const float4*)(Bp);
    rb1 = *(const float4*)(Bp + 4);

    const int sbase = lrow * ASTR + lkq;
    {
        uint4 u;
        u.x = f2tf(ra0.x); u.y = f2tf(ra0.y); u.z = f2tf(ra0.z); u.w = f2tf(ra0.w);
        *(uint4*)&sA[0][sbase] = u;
        u.x = f2tf(ra1.x); u.y = f2tf(ra1.y); u.z = f2tf(ra1.z); u.w = f2tf(ra1.w);
        *(uint4*)&sA[0][sbase + 4] = u;
        u.x = f2tf(rb0.x); u.y = f2tf(rb0.y); u.z = f2tf(rb0.z); u.w = f2tf(rb0.w);
        *(uint4*)&sB[0][sbase] = u;
        u.x = f2tf(rb1.x); u.y = f2tf(rb1.y); u.z = f2tf(rb1.z); u.w = f2tf(rb1.w);
        *(uint4*)&sB[0][sbase + 4] = u;
    }
    __syncthreads();

    const int NT = K / BK;
    int buf = 0;
    for (int kt = 0; kt < NT; kt++) {
        if (kt + 1 < NT) {
            const float* ap = Ap + (kt + 1) * BK;
            const float* bp = Bp + (kt + 1) * BK;
            ra0 = *(const float4*)(ap);
            ra1 = *(const float4*)(ap + 4);
            rb0 = *(const float4*)(bp);
            rb1 = *(const float4*)(bp + 4);
        }

#pragma unroll
        for (int kk = 0; kk < 2; kk++) {
            uint32_t af[4][4], bf[4][2];
            const int ko = kk * 8 + t;
#pragma unroll
            for (int mt = 0; mt < 4; mt++) {
                const int rb = wm + mt * 16 + g;
                af[mt][0] = sA[buf][rb * ASTR + ko];
                af[mt][1] = sA[buf][(rb + 8) * ASTR + ko];
                af[mt][2] = sA[buf][rb * ASTR + ko + 4];
                af[mt][3] = sA[buf][(rb + 8) * ASTR + ko + 4];
            }
#pragma unroll
            for (int nt = 0; nt < 4; nt++) {
                const int nb = wn + nt * 8 + g;
                bf[nt][0] = sB[buf][nb * ASTR + ko];
                bf[nt][1] = sB[buf][nb * ASTR + ko + 4];
            }
#pragma unroll
            for (int mt = 0; mt < 4; mt++)
#pragma unroll
                for (int nt = 0; nt < 4; nt++)
                    mma_tf32(acc[mt * 4 + nt], af[mt], bf[nt]);
        }

        if (kt + 1 < NT) {
            const int nb = buf ^ 1;
            uint4 u;
            u.x = f2tf(ra0.x); u.y = f2tf(ra0.y); u.z = f2tf(ra0.z); u.w = f2tf(ra0.w);
            *(uint4*)&sA[nb][sbase] = u;
            u.x = f2tf(ra1.x); u.y = f2tf(ra1.y); u.z = f2tf(ra1.z); u.w = f2tf(ra1.w);
            *(uint4*)&sA[nb][sbase + 4] = u;
            u.x = f2tf(rb0.x); u.y = f2tf(rb0.y); u.z = f2tf(rb0.z); u.w = f2tf(rb0.w);
            *(uint4*)&sB[nb][sbase] = u;
            u.x = f2tf(rb1.x); u.y = f2tf(rb1.y); u.z = f2tf(rb1.z); u.w = f2tf(rb1.w);
            *(uint4*)&sB[nb][sbase + 4] = u;
            __syncthreads();
            buf = nb;
        }
    }

#pragma unroll
    for (int mt = 0; mt < 4; mt++) {
#pragma unroll
        for (int nt = 0; nt < 4; nt++) {
            const float* a4 = acc[mt * 4 + nt];
            const int row = bm + wm + mt * 16 + g;
            const int col = bn + wn + nt * 8 + 2 * t;
            float bx = 0.f, by = 0.f;
            if (BIAS) { bx = bias[col]; by = bias[col + 1]; }
            float2 v0 = {a4[0] + bx, a4[1] + by};
            float2 v1 = {a4[2] + bx, a4[3] + by};
            *(float2*)(C + (size_t)row * N + col) = v0;
            *(float2*)(C + (size_t)(row + 8) * N + col) = v1;
        }
    }
}

// ---------------------------------------------------------------------------
// TF32 flash attention.
// Block: 256 threads = 8 warps, 128 q-rows of one (b,h); warp owns 16 rows.
// 16 kv-tiles of 64. Q frags in regs (scale*log2e folded pre-rounding).
// sK stride 68 (b-frag 4g+t conflict-free), sV stride 72 (8t+g c.f.),
// sP warp-private stride 68 (a-frag 4g+t c.f.).
// ---------------------------------------------------------------------------
#define KSTR 68
#define VSTR 72
#define PSTR 68
#define FLASH_WORDS (64 * KSTR + 64 * VSTR + 128 * PSTR)
#define FLASH_SMEM  (FLASH_WORDS * 4)

__global__ __launch_bounds__(256)
void flash_tf32(const float* __restrict__ qkv, float* __restrict__ att) {
    extern __shared__ uint32_t fsm[];
    uint32_t* sK  = fsm;
    uint32_t* sV  = fsm + 64 * KSTR;
    uint32_t* sQP = fsm + 64 * KSTR + 64 * VSTR;  // Q staging, then P slices

    const int tid  = threadIdx.x;
    const int lane = tid & 31;
    const int warp = tid >> 5;
    const int g = lane >> 2;
    const int t = lane & 3;
    const int bh = blockIdx.y;
    const int b = bh >> 4;
    const int h = bh & 15;
    const int q0 = blockIdx.x * 128;
    const size_t base = (size_t)b * TSZ * C3;
    const int hoff = h * HDIM;
    const float qscale = 0.125f * 1.44269504088896340736f;  // scale * log2(e)

    // Stage Q (128 x 64), pre-scaled, tf32-rounded
    for (int i = tid; i < 128 * 16; i += 256) {
        int r = i >> 4, c4 = (i & 15) * 4;
        float4 v = *(const float4*)(qkv + base + (size_t)(q0 + r) * C3 + hoff + c4);
        uint4 u;
        u.x = f2tf(v.x * qscale); u.y = f2tf(v.y * qscale);
        u.z = f2tf(v.z * qscale); u.w = f2tf(v.w * qscale);
        *(uint4*)&sQP[r * PSTR + c4] = u;
    }
    __syncthreads();

    // Q fragments -> registers (warp-private rows)
    uint32_t aq[8][4];
    {
        const int rb = warp * 16;
#pragma unroll
        for (int kk = 0; kk < 8; kk++) {
            const int ko = 8 * kk + t;
            aq[kk][0] = sQP[(rb + g) * PSTR + ko];
            aq[kk][1] = sQP[(rb + g + 8) * PSTR + ko];
            aq[kk][2] = sQP[(rb + g) * PSTR + ko + 4];
            aq[kk][3] = sQP[(rb + g + 8) * PSTR + ko + 4];
        }
    }
    uint32_t* sPw = sQP + warp * 16 * PSTR;  // this warp's P slice

    float accO[8][4];
#pragma unroll
    for (int i = 0; i < 8; i++)
#pragma unroll
        for (int j = 0; j < 4; j++) accO[i][j] = 0.f;
    float m0 = -INFINITY, m1 = -INFINITY, l0 = 0.f, l1 = 0.f;

    for (int kt = 0; kt < 16; kt++) {
        __syncthreads();  // prev tile's sK/sV readers done (sQP frag reads done too)
        for (int i = tid; i < 64 * 16; i += 256) {
            int r = i >> 4, c4 = (i & 15) * 4;
            const float* src = qkv + base + (size_t)(kt * 64 + r) * C3 + hoff + c4;
            float4 kv = *(const float4*)(src + DIM);
            float4 vv = *(const float4*)(src + 2 * DIM);
            uint4 uk, uv;
            uk.x = f2tf(kv.x); uk.y = f2tf(kv.y); uk.z = f2tf(kv.z); uk.w = f2tf(kv.w);
            uv.x = f2tf(vv.x); uv.y = f2tf(vv.y); uv.z = f2tf(vv.z); uv.w = f2tf(vv.w);
            *(uint4*)&sK[r * KSTR + c4] = uk;
            *(uint4*)&sV[r * VSTR + c4] = uv;
        }
        __syncthreads();

        // S = Qs * K^T  (base-2 logits)
        float accS[8][4];
#pragma unroll
        for (int i = 0; i < 8; i++)
#pragma unroll
            for (int j = 0; j < 4; j++) accS[i][j] = 0.f;
#pragma unroll
        for (int kk = 0; kk < 8; kk++) {
            const int ko = 8 * kk + t;
#pragma unroll
            for (int nt = 0; nt < 8; nt++) {
                uint32_t b2[2];
                b2[0] = sK[(nt * 8 + g) * KSTR + ko];
                b2[1] = sK[(nt * 8 + g) * KSTR + ko + 4];
                mma_tf32(accS[nt], aq[kk], b2);
            }
        }

        // Online softmax (rows g and g+8), base-2 domain
        float r0 = -INFINITY, r1 = -INFINITY;
#pragma unroll
        for (int nt = 0; nt < 8; nt++) {
            r0 = fmaxf(r0, fmaxf(accS[nt][0], accS[nt][1]));
            r1 = fmaxf(r1, fmaxf(accS[nt][2], accS[nt][3]));
        }
        r0 = fmaxf(r0, __shfl_xor_sync(0xffffffffu, r0, 1));
        r0 = fmaxf(r0, __shfl_xor_sync(0xffffffffu, r0, 2));
        r1 = fmaxf(r1, __shfl_xor_sync(0xffffffffu, r1, 1));
        r1 = fmaxf(r1, __shfl_xor_sync(0xffffffffu, r1, 2));
        const float mn0 = fmaxf(m0, r0);
        const float mn1 = fmaxf(m1, r1);
        const float al0 = exp2f(m0 - mn0);
        const float al1 = exp2f(m1 - mn1);
        float rs0 = 0.f, rs1 = 0.f;
#pragma unroll
        for (int nt = 0; nt < 8; nt++) {
            uint32_t p0 = f2tf(exp2f(accS[nt][0] - mn0));
            uint32_t p1 = f2tf(exp2f(accS[nt][1] - mn0));
            uint32_t p2 = f2tf(exp2f(accS[nt][2] - mn1));
            uint32_t p3 = f2tf(exp2f(accS[nt][3] - mn1));
            rs0 += __uint_as_float(p0) + __uint_as_float(p1);
            rs1 += __uint_as_float(p2) + __uint_as_float(p3);
            uint2 w0 = {p0, p1}, w1 = {p2, p3};
            *(uint2*)&sPw[g * PSTR + nt * 8 + 2 * t] = w0;
            *(uint2*)&sPw[(g + 8) * PSTR + nt * 8 + 2 * t] = w1;
        }
        rs0 += __shfl_xor_sync(0xffffffffu, rs0, 1);
        rs0 += __shfl_xor_sync(0xffffffffu, rs0, 2);
        rs1 += __shfl_xor_sync(0xffffffffu, rs1, 1);
        rs1 += __shfl_xor_sync(0xffffffffu, rs1, 2);
        l0 = l0 * al0 + rs0;
        l1 = l1 * al1 + rs1;
        m0 = mn0; m1 = mn1;
#pragma unroll
        for (int nt = 0; nt < 8; nt++) {
            accO[nt][0] *= al0; accO[nt][1] *= al0;
            accO[nt][2] *= al1; accO[nt][3] *= al1;
        }
        __syncwarp();

        // O += P V
#pragma unroll
        for (int kk = 0; kk < 8; kk++) {
            const int ko = 8 * kk + t;
            uint32_t ap[4];
            ap[0] = sPw[g * PSTR + ko];
            ap[1] = sPw[(g + 8) * PSTR + ko];
            ap[2] = sPw[g * PSTR + ko + 4];
            ap[3] = sPw[(g + 8) * PSTR + ko + 4];
#pragma unroll
            for (int nt = 0; nt < 8; nt++) {
                uint32_t b2[2];
                b2[0] = sV[(8 * kk + t) * VSTR + nt * 8 + g];
                b2[1] = sV[(8 * kk + t + 4) * VSTR + nt * 8 + g];
                mma_tf32(accO[nt], ap, b2);
            }
        }
    }

    // Epilogue: normalize, write [B,T,C]
    const float inv0 = 1.f / l0;
    const float inv1 = 1.f / l1;
    const int r0w = q0 + warp * 16 + g;
    float* o0 = att + (size_t)b * TSZ * DIM + (size_t)r0w * DIM + hoff;
    float* o1 = o0 + (size_t)8 * DIM;
#pragma unroll
    for (int nt = 0; nt < 8; nt++) {
        float2 v0 = {accO[nt][0] * inv0, accO[nt][1] * inv0};
        float2 v1 = {accO[nt][2] * inv1, accO[nt][3] * inv1};
        *(float2*)(o0 + nt * 8 + 2 * t) = v0;
        *(float2*)(o1 + nt * 8 + 2 * t) = v1;
    }
}

// ---------------------------------------------------------------------------
extern "C" void kernel_launch(void* const* d_in, const int* in_sizes, int n_in,
                              void* d_out, int out_size) {
    const float* x     = (const float*)d_in[0];  // [4,1024,1024]
    const float* Wqkv  = (const float*)d_in[1];  // [3072,1024]
    const float* Wproj = (const float*)d_in[2];  // [1024,1024]
    const float* bproj = (const float*)d_in[3];  // [1024]
    float* out = (float*)d_out;                  // [4,1024,1024]

    float *qkv, *att;
    cudaGetSymbolAddress((void**)&qkv, g_qkv);
    cudaGetSymbolAddress((void**)&att, g_att);

    // 1) QKV projection: [4096,1024] x [3072,1024]^T -> [4096,3072]
    tf32_gemm_nt<false><<<dim3(C3 / 128, (BATCH * TSZ) / 128), 256>>>(
        x, Wqkv, nullptr, qkv, BATCH * TSZ, C3, DIM);

    // 2) Attention (tf32 mma flash)
    cudaFuncSetAttribute(flash_tf32, cudaFuncAttributeMaxDynamicSharedMemorySize,
                         FLASH_SMEM);
    flash_tf32<<<dim3(TSZ / 128, BATCH * NHEAD), 256, FLASH_SMEM>>>(qkv, att);

    // 3) Output projection + bias: [4096,1024] x [1024,1024]^T -> [4096,1024]
    tf32_gemm_nt<true><<<dim3(DIM / 128, (BATCH * TSZ) / 128), 256>>>(
        att, Wproj, bproj, out, BATCH * TSZ, DIM, DIM);
}

// round 4
// speedup vs baseline: 2.7069x; 1.2123x over previous
#include <cuda_runtime.h>
#include <math.h>
#include <stdint.h>

// Problem constants
#define BATCH 4
#define TSZ   1024
#define DIM   1024
#define NHEAD 16
#define HDIM  64
#define C3    (3 * DIM)

// Scratch (allocation-free: __device__ globals)
__device__ float g_qkv[BATCH * TSZ * C3];   // [B,T,3C]
__device__ float g_att[BATCH * TSZ * DIM];  // [B,T,C]

// ---------------------------------------------------------------------------
// tf32 / mma / ldmatrix helpers
// ---------------------------------------------------------------------------
__device__ __forceinline__ uint32_t f2tf(float f) {
    uint32_t u;
    asm("cvt.rna.tf32.f32 %0, %1;" : "=r"(u) : "f"(f));
    return u;
}

__device__ __forceinline__ void mma_tf32(float c[4], const uint32_t a[4],
                                         uint32_t b0, uint32_t b1) {
    asm volatile(
        "mma.sync.aligned.m16n8k8.row.col.f32.tf32.tf32.f32 "
        "{%0,%1,%2,%3}, {%4,%5,%6,%7}, {%8,%9}, {%0,%1,%2,%3};"
        : "+f"(c[0]), "+f"(c[1]), "+f"(c[2]), "+f"(c[3])
        : "r"(a[0]), "r"(a[1]), "r"(a[2]), "r"(a[3]), "r"(b0), "r"(b1));
}

__device__ __forceinline__ void ldsm_x4(uint32_t& r0, uint32_t& r1, uint32_t& r2,
                                        uint32_t& r3, uint32_t saddr) {
    asm volatile(
        "ldmatrix.sync.aligned.m8n8.x4.shared.b16 {%0,%1,%2,%3}, [%4];"
        : "=r"(r0), "=r"(r1), "=r"(r2), "=r"(r3)
        : "r"(saddr));
}

// Fragment-lane address components (shared by all kernels):
//  A-frag x4 (m16 x k8): matrices {r0-7/k0, r8-15/k0, r0-7/k4, r8-15/k4}
//  B-frag x4 (n16 x k8): matrices {n0-7/k0, n0-7/k4, n8-15/k0, n8-15/k4}
#define A_ROW(lane) (((lane) & 7) + (((lane) >> 3) & 1) * 8)
#define A_KOF(lane) (((lane) >> 4) * 4)
#define B_ROW(lane) (((lane) & 7) + ((lane) >> 4) * 8)
#define B_KOF(lane) ((((lane) >> 3) & 1) * 4)

// ---------------------------------------------------------------------------
// TF32 GEMM (NT): C[m,n] = sum_k A[m,k]*B[n,k] (+bias[n])
// Block 128x128, BK=16, 8 warps (2x4), warp tile 64x32. LDSM fragment loads.
// ---------------------------------------------------------------------------
#define BK 16
#define ASTR 20

template <bool BIAS>
__global__ __launch_bounds__(256)
void tf32_gemm_nt(const float* __restrict__ A, const float* __restrict__ B,
                  const float* __restrict__ bias, float* __restrict__ C,
                  int M, int N, int K) {
    __shared__ uint32_t sA[2][128 * ASTR];
    __shared__ uint32_t sB[2][128 * ASTR];

    const int tid  = threadIdx.x;
    const int lane = tid & 31;
    const int warp = tid >> 5;
    const int g = lane >> 2;
    const int t = lane & 3;
    const int wm = (warp >> 2) * 64;
    const int wn = (warp & 3) * 32;
    const int bm = blockIdx.y * 128;
    const int bn = blockIdx.x * 128;

    const int lrow = tid >> 1;
    const int lkq  = (tid & 1) * 8;

    const float* Ap = A + (size_t)(bm + lrow) * K + lkq;
    const float* Bp = B + (size_t)(bn + lrow) * K + lkq;

    const uint32_t sAb = (uint32_t)__cvta_generic_to_shared(&sA[0][0]);
    const uint32_t sBb = (uint32_t)__cvta_generic_to_shared(&sB[0][0]);
    const uint32_t BUFB = 128 * ASTR * 4;  // bytes per buffer

    const int ar = A_ROW(lane), ak = A_KOF(lane);
    const int br = B_ROW(lane), bk = B_KOF(lane);

    float acc[16][4];
#pragma unroll
    for (int i = 0; i < 16; i++)
#pragma unroll
        for (int j = 0; j < 4; j++) acc[i][j] = 0.f;

    float4 ra0, ra1, rb0, rb1;
    ra0 = *(const float4*)(Ap);
    ra1 = *(const float4*)(Ap + 4);
    rb0 = *(const float4*)(Bp);
    rb1 = *(const float4*)(Bp + 4);

    const int sbase = lrow * ASTR + lkq;
    {
        uint4 u;
        u.x = f2tf(ra0.x); u.y = f2tf(ra0.y); u.z = f2tf(ra0.z); u.w = f2tf(ra0.w);
        *(uint4*)&sA[0][sbase] = u;
        u.x = f2tf(ra1.x); u.y = f2tf(ra1.y); u.z = f2tf(ra1.z); u.w = f2tf(ra1.w);
        *(uint4*)&sA[0][sbase + 4] = u;
        u.x = f2tf(rb0.x); u.y = f2tf(rb0.y); u.z = f2tf(rb0.z); u.w = f2tf(rb0.w);
        *(uint4*)&sB[0][sbase] = u;
        u.x = f2tf(rb1.x); u.y = f2tf(rb1.y); u.z = f2tf(rb1.z); u.w = f2tf(rb1.w);
        *(uint4*)&sB[0][sbase + 4] = u;
    }
    __syncthreads();

    const int NT = K / BK;
    int buf = 0;
    for (int kt = 0; kt < NT; kt++) {
        if (kt + 1 < NT) {
            const float* ap = Ap + (kt + 1) * BK;
            const float* bp = Bp + (kt + 1) * BK;
            ra0 = *(const float4*)(ap);
            ra1 = *(const float4*)(ap + 4);
            rb0 = *(const float4*)(bp);
            rb1 = *(const float4*)(bp + 4);
        }

        const uint32_t aA = sAb + buf * BUFB;
        const uint32_t aB = sBb + buf * BUFB;
#pragma unroll
        for (int kk = 0; kk < 2; kk++) {
            uint32_t af[4][4];
#pragma unroll
            for (int mt = 0; mt < 4; mt++)
                ldsm_x4(af[mt][0], af[mt][1], af[mt][2], af[mt][3],
                        aA + 4u * ((wm + mt * 16 + ar) * ASTR + kk * 8 + ak));
#pragma unroll
            for (int p = 0; p < 2; p++) {
                uint32_t b0, b1, b2, b3;
                ldsm_x4(b0, b1, b2, b3,
                        aB + 4u * ((wn + p * 16 + br) * ASTR + kk * 8 + bk));
#pragma unroll
                for (int mt = 0; mt < 4; mt++) {
                    mma_tf32(acc[mt * 4 + 2 * p],     af[mt], b0, b1);
                    mma_tf32(acc[mt * 4 + 2 * p + 1], af[mt], b2, b3);
                }
            }
        }

        if (kt + 1 < NT) {
            const int nb = buf ^ 1;
            uint4 u;
            u.x = f2tf(ra0.x); u.y = f2tf(ra0.y); u.z = f2tf(ra0.z); u.w = f2tf(ra0.w);
            *(uint4*)&sA[nb][sbase] = u;
            u.x = f2tf(ra1.x); u.y = f2tf(ra1.y); u.z = f2tf(ra1.z); u.w = f2tf(ra1.w);
            *(uint4*)&sA[nb][sbase + 4] = u;
            u.x = f2tf(rb0.x); u.y = f2tf(rb0.y); u.z = f2tf(rb0.z); u.w = f2tf(rb0.w);
            *(uint4*)&sB[nb][sbase] = u;
            u.x = f2tf(rb1.x); u.y = f2tf(rb1.y); u.z = f2tf(rb1.z); u.w = f2tf(rb1.w);
            *(uint4*)&sB[nb][sbase + 4] = u;
            __syncthreads();
            buf = nb;
        }
    }

#pragma unroll
    for (int mt = 0; mt < 4; mt++) {
#pragma unroll
        for (int nt = 0; nt < 4; nt++) {
            const float* a4 = acc[mt * 4 + nt];
            const int row = bm + wm + mt * 16 + g;
            const int col = bn + wn + nt * 8 + 2 * t;
            float bx = 0.f, by = 0.f;
            if (BIAS) { bx = bias[col]; by = bias[col + 1]; }
            float2 v0 = {a4[0] + bx, a4[1] + by};
            float2 v1 = {a4[2] + bx, a4[3] + by};
            *(float2*)(C + (size_t)row * N + col) = v0;
            *(float2*)(C + (size_t)(row + 8) * N + col) = v1;
        }
    }
}

// ---------------------------------------------------------------------------
// TF32 flash attention with LDSM fragment loads.
// 256 threads = 8 warps, 128 q-rows, 16 kv-tiles of 64.
// sK[j][d] stride 68; sVT[d][j] stride 68 (transposed for B-pattern LDSM);
// sQP: Q staging then warp-private P slices, stride 68.
// ---------------------------------------------------------------------------
#define KSTR 68
#define VSTR 68
#define PSTR 68
#define FLASH_WORDS (64 * KSTR + 64 * VSTR + 128 * PSTR)
#define FLASH_SMEM  (FLASH_WORDS * 4)

__global__ __launch_bounds__(256)
void flash_tf32(const float* __restrict__ qkv, float* __restrict__ att) {
    extern __shared__ uint32_t fsm[];
    uint32_t* sK  = fsm;                         // [64][KSTR]
    uint32_t* sVT = fsm + 64 * KSTR;             // [64][VSTR]  d-major
    uint32_t* sQP = fsm + 64 * KSTR + 64 * VSTR; // [128][PSTR] Q then P

    const int tid  = threadIdx.x;
    const int lane = tid & 31;
    const int warp = tid >> 5;
    const int g = lane >> 2;
    const int t = lane & 3;
    const int bh = blockIdx.y;
    const int b = bh >> 4;
    const int h = bh & 15;
    const int q0 = blockIdx.x * 128;
    const size_t base = (size_t)b * TSZ * C3;
    const int hoff = h * HDIM;
    const float qscale = 0.125f * 1.44269504088896340736f;  // scale * log2(e)

    const uint32_t sKb  = (uint32_t)__cvta_generic_to_shared(sK);
    const uint32_t sVTb = (uint32_t)__cvta_generic_to_shared(sVT);
    const uint32_t sQPb = (uint32_t)__cvta_generic_to_shared(sQP);
    const uint32_t sPwb = sQPb + 4u * (warp * 16 * PSTR);

    const int ar = A_ROW(lane), ak = A_KOF(lane);
    const int br = B_ROW(lane), bk = B_KOF(lane);

    // Stage Q (128 x 64), pre-scaled, tf32-rounded
    for (int i = tid; i < 128 * 16; i += 256) {
        int r = i >> 4, c4 = (i & 15) * 4;
        float4 v = *(const float4*)(qkv + base + (size_t)(q0 + r) * C3 + hoff + c4);
        uint4 u;
        u.x = f2tf(v.x * qscale); u.y = f2tf(v.y * qscale);
        u.z = f2tf(v.z * qscale); u.w = f2tf(v.w * qscale);
        *(uint4*)&sQP[r * PSTR + c4] = u;
    }
    __syncthreads();

    // Q fragments via LDSM (warp-private 16 rows)
    uint32_t aq[8][4];
#pragma unroll
    for (int kk = 0; kk < 8; kk++)
        ldsm_x4(aq[kk][0], aq[kk][1], aq[kk][2], aq[kk][3],
                sQPb + 4u * ((warp * 16 + ar) * PSTR + kk * 8 + ak));

    float accO[8][4];
#pragma unroll
    for (int i = 0; i < 8; i++)
#pragma unroll
        for (int j = 0; j < 4; j++) accO[i][j] = 0.f;
    float m0 = -INFINITY, m1 = -INFINITY, l0 = 0.f, l1 = 0.f;

    // Staging map: lane->row (conflict-free transposed V store)
    const int sr  = (warp & 1) * 32 + lane;  // kv row 0..63
    const int scw = warp >> 1;               // chunk base 0..3

    for (int kt = 0; kt < 16; kt++) {
        __syncthreads();  // prior tile's sK/sVT readers done (Q frags in regs)
#pragma unroll
        for (int k = 0; k < 4; k++) {
            const int c4 = (scw + 4 * k) * 4;
            const float* src = qkv + base + (size_t)(kt * 64 + sr) * C3 + hoff + c4;
            float4 kv = *(const float4*)(src + DIM);
            float4 vv = *(const float4*)(src + 2 * DIM);
            uint4 uk;
            uk.x = f2tf(kv.x); uk.y = f2tf(kv.y); uk.z = f2tf(kv.z); uk.w = f2tf(kv.w);
            *(uint4*)&sK[sr * KSTR + c4] = uk;
            sVT[(c4 + 0) * VSTR + sr] = f2tf(vv.x);
            sVT[(c4 + 1) * VSTR + sr] = f2tf(vv.y);
            sVT[(c4 + 2) * VSTR + sr] = f2tf(vv.z);
            sVT[(c4 + 3) * VSTR + sr] = f2tf(vv.w);
        }
        __syncthreads();

        // S = Qs * K^T (base-2 logits)
        float accS[8][4];
#pragma unroll
        for (int i = 0; i < 8; i++)
#pragma unroll
            for (int j = 0; j < 4; j++) accS[i][j] = 0.f;
#pragma unroll
        for (int kk = 0; kk < 8; kk++) {
#pragma unroll
            for (int p = 0; p < 4; p++) {
                uint32_t k0, k1, k2, k3;
                ldsm_x4(k0, k1, k2, k3,
                        sKb + 4u * ((p * 16 + br) * KSTR + kk * 8 + bk));
                mma_tf32(accS[2 * p],     aq[kk], k0, k1);
                mma_tf32(accS[2 * p + 1], aq[kk], k2, k3);
            }
        }

        // Online softmax (rows g, g+8), base-2 domain
        float r0 = -INFINITY, r1 = -INFINITY;
#pragma unroll
        for (int nt = 0; nt < 8; nt++) {
            r0 = fmaxf(r0, fmaxf(accS[nt][0], accS[nt][1]));
            r1 = fmaxf(r1, fmaxf(accS[nt][2], accS[nt][3]));
        }
        r0 = fmaxf(r0, __shfl_xor_sync(0xffffffffu, r0, 1));
        r0 = fmaxf(r0, __shfl_xor_sync(0xffffffffu, r0, 2));
        r1 = fmaxf(r1, __shfl_xor_sync(0xffffffffu, r1, 1));
        r1 = fmaxf(r1, __shfl_xor_sync(0xffffffffu, r1, 2));
        const float mn0 = fmaxf(m0, r0);
        const float mn1 = fmaxf(m1, r1);
        const float al0 = exp2f(m0 - mn0);
        const float al1 = exp2f(m1 - mn1);
        float rs0 = 0.f, rs1 = 0.f;
        uint32_t* sPw = sQP + warp * 16 * PSTR;
#pragma unroll
        for (int nt = 0; nt < 8; nt++) {
            uint32_t p0 = f2tf(exp2f(accS[nt][0] - mn0));
            uint32_t p1 = f2tf(exp2f(accS[nt][1] - mn0));
            uint32_t p2 = f2tf(exp2f(accS[nt][2] - mn1));
            uint32_t p3 = f2tf(exp2f(accS[nt][3] - mn1));
            rs0 += __uint_as_float(p0) + __uint_as_float(p1);
            rs1 += __uint_as_float(p2) + __uint_as_float(p3);
            uint2 w0 = {p0, p1}, w1 = {p2, p3};
            *(uint2*)&sPw[g * PSTR + nt * 8 + 2 * t] = w0;
            *(uint2*)&sPw[(g + 8) * PSTR + nt * 8 + 2 * t] = w1;
        }
        rs0 += __shfl_xor_sync(0xffffffffu, rs0, 1);
        rs0 += __shfl_xor_sync(0xffffffffu, rs0, 2);
        rs1 += __shfl_xor_sync(0xffffffffu, rs1, 1);
        rs1 += __shfl_xor_sync(0xffffffffu, rs1, 2);
        l0 = l0 * al0 + rs0;
        l1 = l1 * al1 + rs1;
        m0 = mn0; m1 = mn1;
#pragma unroll
        for (int nt = 0; nt < 8; nt++) {
            accO[nt][0] *= al0; accO[nt][1] *= al0;
            accO[nt][2] *= al1; accO[nt][3] *= al1;
        }
        __syncwarp();

        // O += P V  (P via A-frag LDSM, V via B-frag LDSM from sVT)
#pragma unroll
        for (int kk = 0; kk < 8; kk++) {
            uint32_t ap[4];
            ldsm_x4(ap[0], ap[1], ap[2], ap[3],
                    sPwb + 4u * (ar * PSTR + kk * 8 + ak));
#pragma unroll
            for (int p = 0; p < 4; p++) {
                uint32_t v0, v1, v2, v3;
                ldsm_x4(v0, v1, v2, v3,
                        sVTb + 4u * ((p * 16 + br) * VSTR + kk * 8 + bk));
                mma_tf32(accO[2 * p],     ap, v0, v1);
                mma_tf32(accO[2 * p + 1], ap, v2, v3);
            }
        }
    }

    // Epilogue: normalize, write [B,T,C]
    const float inv0 = 1.f / l0;
    const float inv1 = 1.f / l1;
    const int r0w = q0 + warp * 16 + g;
    float* o0 = att + (size_t)b * TSZ * DIM + (size_t)r0w * DIM + hoff;
    float* o1 = o0 + (size_t)8 * DIM;
#pragma unroll
    for (int nt = 0; nt < 8; nt++) {
        float2 v0 = {accO[nt][0] * inv0, accO[nt][1] * inv0};
        float2 v1 = {accO[nt][2] * inv1, accO[nt][3] * inv1};
        *(float2*)(o0 + nt * 8 + 2 * t) = v0;
        *(float2*)(o1 + nt * 8 + 2 * t) = v1;
    }
}

// ---------------------------------------------------------------------------
extern "C" void kernel_launch(void* const* d_in, const int* in_sizes, int n_in,
                              void* d_out, int out_size) {
    const float* x     = (const float*)d_in[0];  // [4,1024,1024]
    const float* Wqkv  = (const float*)d_in[1];  // [3072,1024]
    const float* Wproj = (const float*)d_in[2];  // [1024,1024]
    const float* bproj = (const float*)d_in[3];  // [1024]
    float* out = (float*)d_out;                  // [4,1024,1024]

    float *qkv, *att;
    cudaGetSymbolAddress((void**)&qkv, g_qkv);
    cudaGetSymbolAddress((void**)&att, g_att);

    // 1) QKV projection: [4096,1024] x [3072,1024]^T -> [4096,3072]
    tf32_gemm_nt<false><<<dim3(C3 / 128, (BATCH * TSZ) / 128), 256>>>(
        x, Wqkv, nullptr, qkv, BATCH * TSZ, C3, DIM);

    // 2) Attention (tf32 mma flash, LDSM)
    cudaFuncSetAttribute(flash_tf32, cudaFuncAttributeMaxDynamicSharedMemorySize,
                         FLASH_SMEM);
    flash_tf32<<<dim3(TSZ / 128, BATCH * NHEAD), 256, FLASH_SMEM>>>(qkv, att);

    // 3) Output projection + bias: [4096,1024] x [1024,1024]^T -> [4096,1024]
    tf32_gemm_nt<true><<<dim3(DIM / 128, (BATCH * TSZ) / 128), 256>>>(
        att, Wproj, bproj, out, BATCH * TSZ, DIM, DIM);
}

// round 6
// speedup vs baseline: 2.7570x; 1.0185x over previous
#include <cuda_runtime.h>
#include <math.h>
#include <stdint.h>

// Problem constants
#define BATCH 4
#define TSZ   1024
#define DIM   1024
#define NHEAD 16
#define HDIM  64
#define C3    (3 * DIM)

// Scratch (allocation-free: __device__ globals)
__device__ float g_qkv[BATCH * TSZ * C3];   // [B,T,3C]
__device__ float g_att[BATCH * TSZ * DIM];  // [B,T,C]

// ---------------------------------------------------------------------------
// tf32 / mma / ldmatrix helpers
// ---------------------------------------------------------------------------
__device__ __forceinline__ uint32_t f2tf(float f) {
    uint32_t u;
    asm("cvt.rna.tf32.f32 %0, %1;" : "=r"(u) : "f"(f));
    return u;
}

__device__ __forceinline__ void mma_tf32(float c[4], const uint32_t a[4],
                                         uint32_t b0, uint32_t b1) {
    asm volatile(
        "mma.sync.aligned.m16n8k8.row.col.f32.tf32.tf32.f32 "
        "{%0,%1,%2,%3}, {%4,%5,%6,%7}, {%8,%9}, {%0,%1,%2,%3};"
        : "+f"(c[0]), "+f"(c[1]), "+f"(c[2]), "+f"(c[3])
        : "r"(a[0]), "r"(a[1]), "r"(a[2]), "r"(a[3]), "r"(b0), "r"(b1));
}

__device__ __forceinline__ void ldsm_x4(uint32_t& r0, uint32_t& r1, uint32_t& r2,
                                        uint32_t& r3, uint32_t saddr) {
    asm volatile(
        "ldmatrix.sync.aligned.m8n8.x4.shared.b16 {%0,%1,%2,%3}, [%4];"
        : "=r"(r0), "=r"(r1), "=r"(r2), "=r"(r3)
        : "r"(saddr));
}

// Fragment-lane address components:
//  A-frag x4 (m16 x k8): matrices {r0-7/k0, r8-15/k0, r0-7/k4, r8-15/k4}
//  B-frag x4 (n16 x k8): matrices {n0-7/k0, n0-7/k4, n8-15/k0, n8-15/k4}
#define A_ROW(lane) (((lane) & 7) + (((lane) >> 3) & 1) * 8)
#define A_KOF(lane) (((lane) >> 4) * 4)
#define B_ROW(lane) (((lane) & 7) + ((lane) >> 4) * 8)
#define B_KOF(lane) ((((lane) >> 3) & 1) * 4)

// ---------------------------------------------------------------------------
// TF32 GEMM (NT): C[m,n] = sum_k A[m,k]*B[n,k] (+bias[n])
// Block 128(M) x 256(N), BK=16, 8 warps (2x4), warp tile 64x64.
// Double-buffered dynamic smem; LDSM fragment loads; stride 20 (conflict-free).
// ---------------------------------------------------------------------------
#define BK 16
#define ASTR 20
#define SA_WORDS (128 * ASTR)              // per buffer
#define SB_WORDS (256 * ASTR)
#define GEMM_SMEM ((2 * (SA_WORDS + SB_WORDS)) * 4)

template <bool BIAS>
__global__ __launch_bounds__(256, 1)
void tf32_gemm_nt(const float* __restrict__ A, const float* __restrict__ B,
                  const float* __restrict__ bias, float* __restrict__ C,
                  int M, int N, int K) {
    extern __shared__ uint32_t gsm[];
    // layout: sA0, sB0, sA1, sB1
    uint32_t* sAbuf[2] = {gsm, gsm + SA_WORDS + SB_WORDS};
    uint32_t* sBbuf[2] = {gsm + SA_WORDS, gsm + 2 * SA_WORDS + SB_WORDS};

    const int tid  = threadIdx.x;
    const int lane = tid & 31;
    const int warp = tid >> 5;
    const int g = lane >> 2;
    const int t = lane & 3;
    const int wm = (warp >> 2) * 64;   // 0 or 64
    const int wn = (warp & 3) * 64;    // 0,64,128,192
    const int bm = blockIdx.y * 128;
    const int bn = blockIdx.x * 256;

    const int lrow = tid >> 1;         // 0..127
    const int lkq  = (tid & 1) * 8;    // 0 or 8

    const float* Ap  = A + (size_t)(bm + lrow) * K + lkq;
    const float* Bp0 = B + (size_t)(bn + lrow) * K + lkq;
    const float* Bp1 = B + (size_t)(bn + 128 + lrow) * K + lkq;

    const uint32_t smem0 = (uint32_t)__cvta_generic_to_shared(gsm);
    const uint32_t sAoff[2] = {smem0, smem0 + 4u * (SA_WORDS + SB_WORDS)};
    const uint32_t sBoff[2] = {smem0 + 4u * SA_WORDS,
                               smem0 + 4u * (2 * SA_WORDS + SB_WORDS)};

    const int ar = A_ROW(lane), ak = A_KOF(lane);
    const int br = B_ROW(lane), bk = B_KOF(lane);

    float acc[4][8][4];
#pragma unroll
    for (int i = 0; i < 4; i++)
#pragma unroll
        for (int j = 0; j < 8; j++)
#pragma unroll
            for (int q = 0; q < 4; q++) acc[i][j][q] = 0.f;

    float4 ra0, ra1, rb00, rb01, rb10, rb11;
    ra0  = *(const float4*)(Ap);
    ra1  = *(const float4*)(Ap + 4);
    rb00 = *(const float4*)(Bp0);
    rb01 = *(const float4*)(Bp0 + 4);
    rb10 = *(const float4*)(Bp1);
    rb11 = *(const float4*)(Bp1 + 4);

    const int sbA  = lrow * ASTR + lkq;
    const int sbB0 = lrow * ASTR + lkq;
    const int sbB1 = (128 + lrow) * ASTR + lkq;

#define STAGE(bufi)                                                            \
    do {                                                                       \
        uint4 u;                                                               \
        u.x = f2tf(ra0.x); u.y = f2tf(ra0.y); u.z = f2tf(ra0.z); u.w = f2tf(ra0.w); \
        *(uint4*)&sAbuf[bufi][sbA] = u;                                        \
        u.x = f2tf(ra1.x); u.y = f2tf(ra1.y); u.z = f2tf(ra1.z); u.w = f2tf(ra1.w); \
        *(uint4*)&sAbuf[bufi][sbA + 4] = u;                                    \
        u.x = f2tf(rb00.x); u.y = f2tf(rb00.y); u.z = f2tf(rb00.z); u.w = f2tf(rb00.w); \
        *(uint4*)&sBbuf[bufi][sbB0] = u;                                       \
        u.x = f2tf(rb01.x); u.y = f2tf(rb01.y); u.z = f2tf(rb01.z); u.w = f2tf(rb01.w); \
        *(uint4*)&sBbuf[bufi][sbB0 + 4] = u;                                   \
        u.x = f2tf(rb10.x); u.y = f2tf(rb10.y); u.z = f2tf(rb10.z); u.w = f2tf(rb10.w); \
        *(uint4*)&sBbuf[bufi][sbB1] = u;                                       \
        u.x = f2tf(rb11.x); u.y = f2tf(rb11.y); u.z = f2tf(rb11.z); u.w = f2tf(rb11.w); \
        *(uint4*)&sBbuf[bufi][sbB1 + 4] = u;                                   \
    } while (0)

    STAGE(0);
    __syncthreads();

    const int NT = K / BK;
    int buf = 0;
    for (int kt = 0; kt < NT; kt++) {
        if (kt + 1 < NT) {
            const float* ap  = Ap + (kt + 1) * BK;
            const float* bp0 = Bp0 + (kt + 1) * BK;
            const float* bp1 = Bp1 + (kt + 1) * BK;
            ra0  = *(const float4*)(ap);
            ra1  = *(const float4*)(ap + 4);
            rb00 = *(const float4*)(bp0);
            rb01 = *(const float4*)(bp0 + 4);
            rb10 = *(const float4*)(bp1);
            rb11 = *(const float4*)(bp1 + 4);
        }

        const uint32_t aA = sAoff[buf];
        const uint32_t aB = sBoff[buf];
#pragma unroll
        for (int kk = 0; kk < 2; kk++) {
            uint32_t af[4][4];
#pragma unroll
            for (int mt = 0; mt < 4; mt++)
                ldsm_x4(af[mt][0], af[mt][1], af[mt][2], af[mt][3],
                        aA + 4u * ((wm + mt * 16 + ar) * ASTR + kk * 8 + ak));
#pragma unroll
            for (int p = 0; p < 4; p++) {
                uint32_t b0, b1, b2, b3;
                ldsm_x4(b0, b1, b2, b3,
                        aB + 4u * ((wn + p * 16 + br) * ASTR + kk * 8 + bk));
#pragma unroll
                for (int mt = 0; mt < 4; mt++) {
                    mma_tf32(acc[mt][2 * p],     af[mt], b0, b1);
                    mma_tf32(acc[mt][2 * p + 1], af[mt], b2, b3);
                }
            }
        }

        if (kt + 1 < NT) {
            const int nb = buf ^ 1;
            STAGE(nb);
            __syncthreads();
            buf = nb;
        }
    }

    // Epilogue
#pragma unroll
    for (int mt = 0; mt < 4; mt++) {
#pragma unroll
        for (int nt = 0; nt < 8; nt++) {
            const float* a4 = acc[mt][nt];
            const int row = bm + wm + mt * 16 + g;
            const int col = bn + wn + nt * 8 + 2 * t;
            float bx = 0.f, by = 0.f;
            if (BIAS) { bx = bias[col]; by = bias[col + 1]; }
            float2 v0 = {a4[0] + bx, a4[1] + by};
            float2 v1 = {a4[2] + bx, a4[3] + by};
            *(float2*)(C + (size_t)row * N + col) = v0;
            *(float2*)(C + (size_t)(row + 8) * N + col) = v1;
        }
    }
}

// ---------------------------------------------------------------------------
// TF32 flash attention with LDSM fragment loads (round-4, proven).
// 256 threads = 8 warps, 128 q-rows, 16 kv-tiles of 64.
// ---------------------------------------------------------------------------
#define KSTR 68
#define VSTR 68
#define PSTR 68
#define FLASH_WORDS (64 * KSTR + 64 * VSTR + 128 * PSTR)
#define FLASH_SMEM  (FLASH_WORDS * 4)

__global__ __launch_bounds__(256)
void flash_tf32(const float* __restrict__ qkv, float* __restrict__ att) {
    extern __shared__ uint32_t fsm[];
    uint32_t* sK  = fsm;                         // [64][KSTR]
    uint32_t* sVT = fsm + 64 * KSTR;             // [64][VSTR]  d-major
    uint32_t* sQP = fsm + 64 * KSTR + 64 * VSTR; // [128][PSTR] Q then P

    const int tid  = threadIdx.x;
    const int lane = tid & 31;
    const int warp = tid >> 5;
    const int g = lane >> 2;
    const int t = lane & 3;
    const int bh = blockIdx.y;
    const int b = bh >> 4;
    const int h = bh & 15;
    const int q0 = blockIdx.x * 128;
    const size_t base = (size_t)b * TSZ * C3;
    const int hoff = h * HDIM;
    const float qscale = 0.125f * 1.44269504088896340736f;  // scale * log2(e)

    const uint32_t sKb  = (uint32_t)__cvta_generic_to_shared(sK);
    const uint32_t sVTb = (uint32_t)__cvta_generic_to_shared(sVT);
    const uint32_t sQPb = (uint32_t)__cvta_generic_to_shared(sQP);
    const uint32_t sPwb = sQPb + 4u * (warp * 16 * PSTR);

    const int ar = A_ROW(lane), ak = A_KOF(lane);
    const int br = B_ROW(lane), bk = B_KOF(lane);

    // Stage Q (128 x 64), pre-scaled, tf32-rounded
    for (int i = tid; i < 128 * 16; i += 256) {
        int r = i >> 4, c4 = (i & 15) * 4;
        float4 v = *(const float4*)(qkv + base + (size_t)(q0 + r) * C3 + hoff + c4);
        uint4 u;
        u.x = f2tf(v.x * qscale); u.y = f2tf(v.y * qscale);
        u.z = f2tf(v.z * qscale); u.w = f2tf(v.w * qscale);
        *(uint4*)&sQP[r * PSTR + c4] = u;
    }
    __syncthreads();

    // Q fragments via LDSM (warp-private 16 rows)
    uint32_t aq[8][4];
#pragma unroll
    for (int kk = 0; kk < 8; kk++)
        ldsm_x4(aq[kk][0], aq[kk][1], aq[kk][2], aq[kk][3],
                sQPb + 4u * ((warp * 16 + ar) * PSTR + kk * 8 + ak));

    float accO[8][4];
#pragma unroll
    for (int i = 0; i < 8; i++)
#pragma unroll
        for (int j = 0; j < 4; j++) accO[i][j] = 0.f;
    float m0 = -INFINITY, m1 = -INFINITY, l0 = 0.f, l1 = 0.f;

    // Staging map: lane->row (conflict-free transposed V store)
    const int sr  = (warp & 1) * 32 + lane;  // kv row 0..63
    const int scw = warp >> 1;               // chunk base 0..3

    for (int kt = 0; kt < 16; kt++) {
        __syncthreads();  // prior tile's sK/sVT readers done (Q frags in regs)
#pragma unroll
        for (int k = 0; k < 4; k++) {
            const int c4 = (scw + 4 * k) * 4;
            const float* src = qkv + base + (size_t)(kt * 64 + sr) * C3 + hoff + c4;
            float4 kv = *(const float4*)(src + DIM);
            float4 vv = *(const float4*)(src + 2 * DIM);
            uint4 uk;
            uk.x = f2tf(kv.x); uk.y = f2tf(kv.y); uk.z = f2tf(kv.z); uk.w = f2tf(kv.w);
            *(uint4*)&sK[sr * KSTR + c4] = uk;
            sVT[(c4 + 0) * VSTR + sr] = f2tf(vv.x);
            sVT[(c4 + 1) * VSTR + sr] = f2tf(vv.y);
            sVT[(c4 + 2) * VSTR + sr] = f2tf(vv.z);
            sVT[(c4 + 3) * VSTR + sr] = f2tf(vv.w);
        }
        __syncthreads();

        // S = Qs * K^T (base-2 logits)
        float accS[8][4];
#pragma unroll
        for (int i = 0; i < 8; i++)
#pragma unroll
            for (int j = 0; j < 4; j++) accS[i][j] = 0.f;
#pragma unroll
        for (int kk = 0; kk < 8; kk++) {
#pragma unroll
            for (int p = 0; p < 4; p++) {
                uint32_t k0, k1, k2, k3;
                ldsm_x4(k0, k1, k2, k3,
                        sKb + 4u * ((p * 16 + br) * KSTR + kk * 8 + bk));
                mma_tf32(accS[2 * p],     aq[kk], k0, k1);
                mma_tf32(accS[2 * p + 1], aq[kk], k2, k3);
            }
        }

        // Online softmax (rows g, g+8), base-2 domain
        float r0 = -INFINITY, r1 = -INFINITY;
#pragma unroll
        for (int nt = 0; nt < 8; nt++) {
            r0 = fmaxf(r0, fmaxf(accS[nt][0], accS[nt][1]));
            r1 = fmaxf(r1, fmaxf(accS[nt][2], accS[nt][3]));
        }
        r0 = fmaxf(r0, __shfl_xor_sync(0xffffffffu, r0, 1));
        r0 = fmaxf(r0, __shfl_xor_sync(0xffffffffu, r0, 2));
        r1 = fmaxf(r1, __shfl_xor_sync(0xffffffffu, r1, 1));
        r1 = fmaxf(r1, __shfl_xor_sync(0xffffffffu, r1, 2));
        const float mn0 = fmaxf(m0, r0);
        const float mn1 = fmaxf(m1, r1);
        const float al0 = exp2f(m0 - mn0);
        const float al1 = exp2f(m1 - mn1);
        float rs0 = 0.f, rs1 = 0.f;
        uint32_t* sPw = sQP + warp * 16 * PSTR;
#pragma unroll
        for (int nt = 0; nt < 8; nt++) {
            uint32_t p0 = f2tf(exp2f(accS[nt][0] - mn0));
            uint32_t p1 = f2tf(exp2f(accS[nt][1] - mn0));
            uint32_t p2 = f2tf(exp2f(accS[nt][2] - mn1));
            uint32_t p3 = f2tf(exp2f(accS[nt][3] - mn1));
            rs0 += __uint_as_float(p0) + __uint_as_float(p1);
            rs1 += __uint_as_float(p2) + __uint_as_float(p3);
            uint2 w0 = {p0, p1}, w1 = {p2, p3};
            *(uint2*)&sPw[g * PSTR + nt * 8 + 2 * t] = w0;
            *(uint2*)&sPw[(g + 8) * PSTR + nt * 8 + 2 * t] = w1;
        }
        rs0 += __shfl_xor_sync(0xffffffffu, rs0, 1);
        rs0 += __shfl_xor_sync(0xffffffffu, rs0, 2);
        rs1 += __shfl_xor_sync(0xffffffffu, rs1, 1);
        rs1 += __shfl_xor_sync(0xffffffffu, rs1, 2);
        l0 = l0 * al0 + rs0;
        l1 = l1 * al1 + rs1;
        m0 = mn0; m1 = mn1;
#pragma unroll
        for (int nt = 0; nt < 8; nt++) {
            accO[nt][0] *= al0; accO[nt][1] *= al0;
            accO[nt][2] *= al1; accO[nt][3] *= al1;
        }
        __syncwarp();

        // O += P V  (P via A-frag LDSM, V via B-frag LDSM from sVT)
#pragma unroll
        for (int kk = 0; kk < 8; kk++) {
            uint32_t ap[4];
            ldsm_x4(ap[0], ap[1], ap[2], ap[3],
                    sPwb + 4u * (ar * PSTR + kk * 8 + ak));
#pragma unroll
            for (int p = 0; p < 4; p++) {
                uint32_t v0, v1, v2, v3;
                ldsm_x4(v0, v1, v2, v3,
                        sVTb + 4u * ((p * 16 + br) * VSTR + kk * 8 + bk));
                mma_tf32(accO[2 * p],     ap, v0, v1);
                mma_tf32(accO[2 * p + 1], ap, v2, v3);
            }
        }
    }

    // Epilogue: normalize, write [B,T,C]
    const float inv0 = 1.f / l0;
    const float inv1 = 1.f / l1;
    const int r0w = q0 + warp * 16 + g;
    float* o0 = att + (size_t)b * TSZ * DIM + (size_t)r0w * DIM + hoff;
    float* o1 = o0 + (size_t)8 * DIM;
#pragma unroll
    for (int nt = 0; nt < 8; nt++) {
        float2 v0 = {accO[nt][0] * inv0, accO[nt][1] * inv0};
        float2 v1 = {accO[nt][2] * inv1, accO[nt][3] * inv1};
        *(float2*)(o0 + nt * 8 + 2 * t) = v0;
        *(float2*)(o1 + nt * 8 + 2 * t) = v1;
    }
}

// ---------------------------------------------------------------------------
extern "C" void kernel_launch(void* const* d_in, const int* in_sizes, int n_in,
                              void* d_out, int out_size) {
    const float* x     = (const float*)d_in[0];  // [4,1024,1024]
    const float* Wqkv  = (const float*)d_in[1];  // [3072,1024]
    const float* Wproj = (const float*)d_in[2];  // [1024,1024]
    const float* bproj = (const float*)d_in[3];  // [1024]
    float* out = (float*)d_out;                  // [4,1024,1024]

    float *qkv, *att;
    cudaGetSymbolAddress((void**)&qkv, g_qkv);
    cudaGetSymbolAddress((void**)&att, g_att);

    cudaFuncSetAttribute(tf32_gemm_nt<false>,
                         cudaFuncAttributeMaxDynamicSharedMemorySize, GEMM_SMEM);
    cudaFuncSetAttribute(tf32_gemm_nt<true>,
                         cudaFuncAttributeMaxDynamicSharedMemorySize, GEMM_SMEM);
    cudaFuncSetAttribute(flash_tf32,
                         cudaFuncAttributeMaxDynamicSharedMemorySize, FLASH_SMEM);

    // 1) QKV projection: [4096,1024] x [3072,1024]^T -> [4096,3072]
    tf32_gemm_nt<false><<<dim3(C3 / 256, (BATCH * TSZ) / 128), 256, GEMM_SMEM>>>(
        x, Wqkv, nullptr, qkv, BATCH * TSZ, C3, DIM);

    // 2) Attention (tf32 mma flash, LDSM)
    flash_tf32<<<dim3(TSZ / 128, BATCH * NHEAD), 256, FLASH_SMEM>>>(qkv, att);

    // 3) Output projection + bias: [4096,1024] x [1024,1024]^T -> [4096,1024]
    tf32_gemm_nt<true><<<dim3(DIM / 256, (BATCH * TSZ) / 128), 256, GEMM_SMEM>>>(
        att, Wproj, bproj, out, BATCH * TSZ, DIM, DIM);
}